// round 7
// baseline (speedup 1.0000x reference)
#include <cuda_runtime.h>
#include <math.h>

#define TT 4096
#define BB 32
#define NH 100
#define NM 65

// ---- scratch (__device__ globals: allocations forbidden) ----
__device__ __align__(16) float g_tfac[TT*NH];
__device__ __align__(16) float g_nfac[TT*NM];
__device__ __align__(16) float g_hmid[(size_t)BB*TT*NH];  // 52.4MB
__device__ __align__(16) float g_a[TT*NH];
__device__ __align__(16) float g_c[TT*NH];
__device__ __align__(16) float g_hmean[TT*NH];
__device__ float g_cmean[TT];
__device__ float g_sreso[TT];

__device__ __forceinline__ float wmax(float v){
  #pragma unroll
  for (int d=16; d; d>>=1) v = fmaxf(v, __shfl_xor_sync(0xffffffffu, v, d));
  return v;
}
__device__ __forceinline__ float wsum(float v){
  #pragma unroll
  for (int d=16; d; d>>=1) v += __shfl_xor_sync(0xffffffffu, v, d);
  return v;
}

// ---- K0: per-(t,j) sinusoidal factors, flat launch ------------------------
__global__ void k_factors(){
  int idx = blockIdx.x*blockDim.x + threadIdx.x;
  const int TOT = TT*(NH+NM);
  if (idx >= TOT) return;
  int t = idx / (NH+NM);
  int j = idx - t*(NH+NM);
  const double INC  = (double)(float)1.0053096491487339;   // f32(2pi*40*64/16000)
  const double WRAP = (double)(float)6.283185307179586;    // f32(2pi)
  float phase = (float)fmod((double)(t+1)*INC, WRAP);
  if (j < NH) {
    float off = (float)((double)j * (4.71238898038469/99.0));
    g_tfac[t*NH+j] = 1.0f + 0.225f*sinf(phase + off);
  } else {
    int m = j - NH;
    float rb = (float)m * 7.853981633974483f;
    g_nfac[t*NM+m] = 1.0f + 0.6f*sinf(rb + phase);
  }
}

// ---- K1: stats (blocks [0,TT)) + noise stream (blocks >= TT) --------------
__global__ __launch_bounds__(512) void k_stats(const float* __restrict__ harm,
                                               const float4* __restrict__ nin,
                                               float4* __restrict__ outn){
  int bid = blockIdx.x;
  if (bid >= TT){
    // fused noise epilogue: n = noise * nfac  (grid-stride, float4)
    const int NVN = BB*TT*NM/4;
    int idx = (bid - TT)*512 + threadIdx.x;
    int stride = (gridDim.x - TT)*512;
    for (int j = idx; j < NVN; j += stride){
      int fi = j % (TT*NM/4);
      float4 v = nin[j];
      float4 f = reinterpret_cast<const float4*>(g_nfac)[fi];
      v.x *= f.x; v.y *= f.y; v.z *= f.z; v.w *= f.w;
      outn[j] = v;
    }
    return;
  }
  int t = bid;
  int warp = threadIdx.x>>5, lane = threadIdx.x&31;     // 16 warps x 2 rows
  __shared__ float4 s_tfac[25];
  __shared__ float  s_hsum[NH];
  __shared__ float  s_csum;
  if (threadIdx.x < 25) s_tfac[threadIdx.x] =
      reinterpret_cast<const float4*>(g_tfac + t*NH)[threadIdx.x];
  if (threadIdx.x < NH) s_hsum[threadIdx.x] = 0.f;
  if (threadIdx.x == 0) s_csum = 0.f;
  __syncthreads();
  bool act = lane < 25;
  float4 f = act ? s_tfac[lane] : make_float4(0.f,0.f,0.f,0.f);
  float4 acc = make_float4(0.f,0.f,0.f,0.f);
  float cacc = 0.f;
  float k0 = (float)(lane*4);
  #pragma unroll
  for (int r=0;r<2;++r){
    int b = warp + r*16;
    size_t rowoff = ((size_t)b*TT + t)*NH;
    float4 x = act ? reinterpret_cast<const float4*>(harm + rowoff)[lane]
                   : make_float4(0.f,0.f,0.f,0.f);
    float mo = fmaxf(fmaxf(x.x,x.y), fmaxf(x.z,x.w));
    mo = fmaxf(wmax(mo), 1e-6f);
    float4 s;
    s.x = __powf(fmaxf(x.x,1e-6f), 3.4f);
    s.y = __powf(fmaxf(x.y,1e-6f), 3.4f);
    s.z = __powf(fmaxf(x.z,1e-6f), 3.4f);
    s.w = __powf(fmaxf(x.w,1e-6f), 3.4f);
    float ml = act ? fmaxf(fmaxf(s.x,s.y), fmaxf(s.z,s.w)) : 0.f;
    float ms = fmaxf(wmax(ml), 1e-6f);
    float ratio = mo/ms;
    float4 h;
    h.x = s.x*ratio*f.x; h.y = s.y*ratio*f.y;
    h.z = s.z*ratio*f.z; h.w = s.w*ratio*f.w;
    float num = h.x*k0 + h.y*(k0+1.f) + h.z*(k0+2.f) + h.w*(k0+3.f);
    float den = h.x+h.y+h.z+h.w;
    num = wsum(num); den = wsum(den);
    if (lane==0) cacc += num / fmaxf(den, 1e-6f);
    if (act) reinterpret_cast<float4*>(g_hmid + rowoff)[lane] = h;
    acc.x+=h.x; acc.y+=h.y; acc.z+=h.z; acc.w+=h.w;
  }
  if (act){
    atomicAdd(&s_hsum[lane*4+0], acc.x);
    atomicAdd(&s_hsum[lane*4+1], acc.y);
    atomicAdd(&s_hsum[lane*4+2], acc.z);
    atomicAdd(&s_hsum[lane*4+3], acc.w);
  }
  if (lane==0) atomicAdd(&s_csum, cacc);
  __syncthreads();
  if (threadIdx.x < NH) g_hmean[t*NH+threadIdx.x] = s_hsum[threadIdx.x] * (1.f/32.f);
  if (threadIdx.x == 0) g_cmean[t] = s_csum * (1.f/32.f);
}

// ---- K2: fb affine scan + clock prefix sum (256 thr x 16 elems, double) ---
__global__ void k_scan(){
  __shared__ double s_clk[TT];
  __shared__ double s_wa[8], s_wb[8], s_ws[8];
  int tid = threadIdx.x;
  int lane = tid & 31, warp = tid >> 5;
  int base = tid * 16;
  const double RATE_K = 0.725 * 6.283185307179586 * 0.004;
  double v = 0.0;
  #pragma unroll
  for (int j=0;j<16;++j){
    double u = 0.1*(((double)g_cmean[base+j] - 30.0)/40.0);
    v = 0.9*v + u;
  }
  double a = 0.18530201888518416;  // 0.9^16
  double b = v;
  #pragma unroll
  for (int d=1; d<32; d<<=1){
    double pa = __shfl_up_sync(0xffffffffu, a, d);
    double pb = __shfl_up_sync(0xffffffffu, b, d);
    if (lane >= d){ b = a*pb + b; a = a*pa; }
  }
  if (lane == 31){ s_wa[warp]=a; s_wb[warp]=b; }
  __syncthreads();
  double wpre = 0.0;
  for (int w=0; w<warp; ++w) wpre = s_wa[w]*wpre + s_wb[w];
  double ae = __shfl_up_sync(0xffffffffu, a, 1);
  double be = __shfl_up_sync(0xffffffffu, b, 1);
  double fb = (lane==0) ? wpre : (ae*wpre + be);
  double csum = 0.0;
  #pragma unroll
  for (int j=0;j<16;++j){
    double u = 0.1*(((double)g_cmean[base+j] - 30.0)/40.0);
    fb = 0.9*fb + u;
    csum += RATE_K * (1.0 + 0.4*fb);
    s_clk[base+j] = csum;
  }
  double S = csum, ss = S;
  #pragma unroll
  for (int d=1; d<32; d<<=1){
    double p = __shfl_up_sync(0xffffffffu, ss, d);
    if (lane >= d) ss += p;
  }
  if (lane == 31) s_ws[warp] = ss;
  __syncthreads();
  double off = 0.0;
  for (int w=0; w<warp; ++w) off += s_ws[w];
  double excl = off + ss - S;
  #pragma unroll
  for (int j=0;j<16;++j){
    double c = fmod(excl + s_clk[base+j], 6.283185307179586);
    g_sreso[base+j] = 0.4f * sinf((float)c);
  }
}

// ---- K3: per-(t,k) affine tables a,c — flat float4 launch -----------------
__global__ void k_combine(){
  int q = blockIdx.x*blockDim.x + threadIdx.x;     // float4 index into TT*NH/4
  const int NQ = TT*NH/4;
  if (q >= NQ) return;
  int t = q / 25;
  int k4 = (q - t*25)*4;
  float sr = g_sreso[t];
  float4 rel;
  rel.x = (float)k4/99.0f*2.0f - 1.0f;
  rel.y = (float)(k4+1)/99.0f*2.0f - 1.0f;
  rel.z = (float)(k4+2)/99.0f*2.0f - 1.0f;
  rel.w = (float)(k4+3)/99.0f*2.0f - 1.0f;
  float scale = (t==0) ? 1.0f : 0.6f;
  float4 a;
  a.x = scale*(1.0f + sr*rel.x); a.y = scale*(1.0f + sr*rel.y);
  a.z = scale*(1.0f + sr*rel.z); a.w = scale*(1.0f + sr*rel.w);
  float4 c = make_float4(0.f,0.f,0.f,0.f);
  if (t >= 149){
    float srp = g_sreso[t-149];
    float4 hm = reinterpret_cast<const float4*>(g_hmean)[(t-149)*25 + (q - t*25)];
    c.x = 0.4f*(1.0f + srp*rel.x)*hm.x;
    c.y = 0.4f*(1.0f + srp*rel.y)*hm.y;
    c.z = 0.4f*(1.0f + srp*rel.z)*hm.z;
    c.w = 0.4f*(1.0f + srp*rel.w)*hm.w;
  }
  reinterpret_cast<float4*>(g_a)[q] = a;
  reinterpret_cast<float4*>(g_c)[q] = c;
}

// ---- K4: harmonic epilogue only: h = a*h_mid + c --------------------------
__global__ __launch_bounds__(256) void k_out(float4* __restrict__ outh){
  const int NVH = BB*TT*NH/4;
  int i = blockIdx.x*blockDim.x + threadIdx.x;
  if (i >= NVH) return;
  int tk = i % (TT*NH/4);
  float4 v = reinterpret_cast<const float4*>(g_hmid)[i];
  float4 a = reinterpret_cast<const float4*>(g_a)[tk];
  float4 c = reinterpret_cast<const float4*>(g_c)[tk];
  float4 o;
  o.x = fmaf(a.x, v.x, c.x); o.y = fmaf(a.y, v.y, c.y);
  o.z = fmaf(a.z, v.z, c.z); o.w = fmaf(a.w, v.w, c.w);
  outh[i] = o;
}

extern "C" void kernel_launch(void* const* d_in, const int* in_sizes, int n_in,
                              void* d_out, int out_size){
  const float* harm  = (const float*)d_in[0];
  const float* noise = (const float*)d_in[1];
  float* outh = (float*)d_out;
  float* outn = outh + (size_t)BB*TT*NH;
  k_factors<<<(TT*(NH+NM)+255)/256, 256>>>();
  k_stats  <<<TT + 2048, 512>>>(harm, (const float4*)noise, (float4*)outn);
  k_scan   <<<1, 256>>>();
  k_combine<<<(TT*NH/4 + 255)/256, 256>>>();
  k_out    <<<(BB*TT*NH/4 + 255)/256, 256>>>((float4*)outh);
}